// round 15
// baseline (speedup 1.0000x reference)
#include <cuda_runtime.h>
#include <cuda_bf16.h>
#include <cstdint>

#define BATCH 64
#define C576  576
#define HW49  49
#define NEDGE 24

__device__ float g_bufA[BATCH*C576*HW49];
__device__ float g_bufB[BATCH*C576*HW49];
__device__ float g_first[BATCH*C576*HW49];
__device__ float g_second[BATCH*C576*HW49];
__device__ float g_msgs[NEDGE*BATCH*64*HW49];
__device__ float g_head[BATCH*C576*196];
__device__ __nv_bfloat16 g_whi[7L*9*576*576];
__device__ __nv_bfloat16 g_wlo[7L*9*576*576];
__device__ __nv_bfloat16 g_hA[BATCH*C576*HW49];
__device__ __nv_bfloat16 g_lA[BATCH*C576*HW49];
__device__ __nv_bfloat16 g_hB[BATCH*C576*HW49];
__device__ __nv_bfloat16 g_lB[BATCH*C576*HW49];

__constant__ int c_esrc[NEDGE] = {1,3, 0,2,4, 1,5, 0,4,6, 1,3,5,7, 2,4,8, 3,7, 4,6,8, 5,7};
__constant__ int c_doff[10]    = {0,2,5,7,10,14,17,19,22,24};
__constant__ int c_ocb[5]      = {0, 128, 256, 384, 448};

typedef unsigned long long u64t;
__device__ __forceinline__ u64t pack2(float x, float y) {
    u64t r; asm("mov.b64 %0, {%1, %2};" : "=l"(r) : "f"(x), "f"(y)); return r;
}
__device__ __forceinline__ u64t fma2(u64t a, u64t b, u64t c) {
    u64t d; asm("fma.rn.f32x2 %0, %1, %2, %3;" : "=l"(d) : "l"(a), "l"(b), "l"(c)); return d;
}
__device__ __forceinline__ void unpack2(u64t p, float& x, float& y) {
    asm("mov.b64 {%0, %1}, %2;" : "=f"(x), "=f"(y) : "l"(p));
}
__device__ __forceinline__ uint32_t smem_u32(const void* p) {
    uint32_t a;
    asm("{ .reg .u64 t; cvta.to.shared.u64 t, %1; cvt.u32.u64 %0, t; }" : "=r"(a) : "l"(p));
    return a;
}
__device__ __forceinline__ void ldsm_x4(uint32_t* r, uint32_t addr) {
    asm volatile("ldmatrix.sync.aligned.m8n8.x4.shared.b16 {%0,%1,%2,%3}, [%4];"
        : "=r"(r[0]), "=r"(r[1]), "=r"(r[2]), "=r"(r[3]) : "r"(addr));
}
__device__ __forceinline__ void ldsm_x2(uint32_t* r, uint32_t addr) {
    asm volatile("ldmatrix.sync.aligned.m8n8.x2.shared.b16 {%0,%1}, [%2];"
        : "=r"(r[0]), "=r"(r[1]) : "r"(addr));
}
__device__ __forceinline__ void mma_bf16(float* c, const uint32_t* a, const uint32_t* b) {
    asm volatile(
        "mma.sync.aligned.m16n8k16.row.col.f32.bf16.bf16.f32 "
        "{%0,%1,%2,%3}, {%4,%5,%6,%7}, {%8,%9}, {%0,%1,%2,%3};"
        : "+f"(c[0]), "+f"(c[1]), "+f"(c[2]), "+f"(c[3])
        : "r"(a[0]), "r"(a[1]), "r"(a[2]), "r"(a[3]), "r"(b[0]), "r"(b[1]));
}

// ---- weight split: fp32 -> bf16 hi/lo, layout [(l*9+t)*576+oc][ic] ----
__global__ void split_w_kernel(const float* __restrict__ w,
                               __nv_bfloat16* __restrict__ whi,
                               __nv_bfloat16* __restrict__ wlo)
{
    long i = (long)blockIdx.x * blockDim.x + threadIdx.x;
    if (i >= 7L*9*576*576) return;
    int ic = i % 576; long r = i / 576;
    int oc = r % 576; long r2 = r / 576;
    int t  = r2 % 9;  int l = (int)(r2 / 9);
    float v = w[(((long)(l*576 + oc))*576 + ic)*9 + t];
    __nv_bfloat16 hi = __float2bfloat16(v);
    whi[i] = hi;
    wlo[i] = __float2bfloat16(v - __bfloat162float(hi));
}

// =====================================================================
// conv1 via mma.sync bf16 hi/lo implicit GEMM, taps folded into K.
// grid (5 Mtiles, 32 bpairs), block 256 (8 warps: 2M x 4N).
// Per ic-chunk (16 ic): K = 144 = 9 taps x 16 ic (t-major).
// smem (dynamic, stride 152 elems = 304B, conflict-free for ldmatrix):
//   AsH 0, AsL 38912, BsH 77824, BsL 116736,
//   aH_s 155648 (5376), aL_s 161024 (5376), sred 166400, ssred 166656
// =====================================================================
#define STR 152
#define CG_SMEM 166912
__global__ __launch_bounds__(256, 1) void conv_gemm_kernel(
    const __nv_bfloat16* __restrict__ actH, const __nv_bfloat16* __restrict__ actL,
    const __nv_bfloat16* __restrict__ wHi,  const __nv_bfloat16* __restrict__ wLo,
    const float* __restrict__ bias, const float* __restrict__ gamma,
    const float* __restrict__ beta, float* __restrict__ dstF,
    __nv_bfloat16* __restrict__ outH, __nv_bfloat16* __restrict__ outL)
{
    extern __shared__ char sm[];
    __nv_bfloat16* AsH  = (__nv_bfloat16*)(sm);
    __nv_bfloat16* AsL  = (__nv_bfloat16*)(sm + 38912);
    __nv_bfloat16* BsH  = (__nv_bfloat16*)(sm + 77824);
    __nv_bfloat16* BsL  = (__nv_bfloat16*)(sm + 116736);
    __nv_bfloat16* aH_s = (__nv_bfloat16*)(sm + 155648);   // [2][16][84]
    __nv_bfloat16* aL_s = (__nv_bfloat16*)(sm + 161024);
    float* sred  = (float*)(sm + 166400);
    float* ssred = (float*)(sm + 166656);

    const int tid  = threadIdx.x;
    const int lane = tid & 31, w = tid >> 5;
    const int wm = w >> 2, wn = w & 3;
    const int ocb = c_ocb[blockIdx.x];
    const int b0  = blockIdx.y * 2;

    float acc[4][4][4];
#pragma unroll
    for (int i = 0; i < 4; i++)
#pragma unroll
        for (int j = 0; j < 4; j++)
#pragma unroll
            for (int r = 0; r < 4; r++) acc[i][j][r] = 0.f;

    // zero B rows 98..127 once (never rewritten)
    for (int i = tid; i < 30*STR; i += 256) {
        BsH[98*STR + i] = __nv_bfloat16(0.f);
        BsL[98*STR + i] = __nv_bfloat16(0.f);
    }

    const uint32_t asH = smem_u32(AsH), asL = smem_u32(AsL);
    const uint32_t bsH = smem_u32(BsH), bsL = smem_u32(BsL);
    const uint32_t aOff = (uint32_t)(lane & 15)*(STR*2) + (uint32_t)(lane >> 4)*16;
    const uint32_t bOff = (uint32_t)(lane & 7)*(STR*2) + (uint32_t)((lane >> 3) & 1)*16;

    for (int icc = 0; icc < 36; icc++) {
        const int ic0 = icc * 16;
        // stage padded activation frames (2 b x 16 ic x 9x9)
        for (int i = tid; i < 2592; i += 256) {
            int b = i / 1296; int r = i % 1296;
            int icl = r / 81; int q = r % 81;
            int y = q / 9, x = q % 9;
            __nv_bfloat16 vh = __nv_bfloat16(0.f), vl = __nv_bfloat16(0.f);
            if (y >= 1 && y <= 7 && x >= 1 && x <= 7) {
                long gi = ((long)(b0 + b)*C576 + ic0 + icl)*49 + (y-1)*7 + (x-1);
                vh = actH[gi]; vl = actL[gi];
            }
            aH_s[(b*16 + icl)*84 + q] = vh;
            aL_s[(b*16 + icl)*84 + q] = vl;
        }
        __syncthreads();
        // build B once: B[n][t*16+icl] = act[icl][pixel shifted by tap t]
        for (int i = tid; i < 98*144; i += 256) {
            int n = i / 144, k = i % 144;
            int t = k >> 4, icl = k & 15;
            int b = (n >= 49); int p = n - b*49;
            int q = (p/7 + t/3)*9 + (p%7 + t%3);
            BsH[n*STR + k] = aH_s[(b*16 + icl)*84 + q];
            BsL[n*STR + k] = aL_s[(b*16 + icl)*84 + q];
        }
        // stage A: 128 oc x 144 k (uint4 = 8 elems per load)
        for (int i = tid; i < 2304; i += 256) {
            int r = i / 18, c = i % 18;
            int t = c >> 1, half = c & 1;
            long gofs = ((long)(t*576 + ocb + r))*576 + ic0 + half*8;
            *(uint4*)&AsH[r*STR + t*16 + half*8] = *(const uint4*)&wHi[gofs];
            *(uint4*)&AsL[r*STR + t*16 + half*8] = *(const uint4*)&wLo[gofs];
        }
        __syncthreads();
#pragma unroll 1
        for (int j = 0; j < 9; j++) {
            uint32_t fAH[4][4], fAL[4][4], fBH[4][2], fBL[4][2];
            const uint32_t jb = (uint32_t)j*32;
#pragma unroll
            for (int mf = 0; mf < 4; mf++) {
                uint32_t off = (uint32_t)(wm*64 + mf*16)*(STR*2) + aOff + jb;
                ldsm_x4(fAH[mf], asH + off);
                ldsm_x4(fAL[mf], asL + off);
            }
#pragma unroll
            for (int nf = 0; nf < 4; nf++) {
                uint32_t off = (uint32_t)(wn*32 + nf*8)*(STR*2) + bOff + jb;
                ldsm_x2(fBH[nf], bsH + off);
                ldsm_x2(fBL[nf], bsL + off);
            }
#pragma unroll
            for (int mf = 0; mf < 4; mf++)
#pragma unroll
                for (int nf = 0; nf < 4; nf++) {
                    mma_bf16(acc[mf][nf], fAH[mf], fBH[nf]);
                    mma_bf16(acc[mf][nf], fAH[mf], fBL[nf]);
                    mma_bf16(acc[mf][nf], fAL[mf], fBH[nf]);
                }
        }
        __syncthreads();
    }

    // ---- epilogue: bias + GN(36) + ReLU + stores (f32 + bf16 hi/lo) ----
    const int mrow  = lane >> 2;
    const int ncol0 = 2*(lane & 3);
    float mean_[4][2], inv_[4][2];
#pragma unroll
    for (int mf = 0; mf < 4; mf++) {
        int m0 = wm*64 + mf*16 + mrow;
        float bv0 = bias[ocb + m0], bv1 = bias[ocb + m0 + 8];
        float s0 = 0.f, s1 = 0.f, q0 = 0.f, q1 = 0.f;
#pragma unroll
        for (int nf = 0; nf < 4; nf++) {
            int nb = wn*32 + nf*8 + ncol0;
#pragma unroll
            for (int r = 0; r < 4; r++) {
                int n = nb + (r & 1);
                float v = acc[mf][nf][r] + ((r < 2) ? bv0 : bv1);
                acc[mf][nf][r] = v;
                if (n < 49)      { s0 += v; q0 += v*v; }
                else if (n < 98) { s1 += v; q1 += v*v; }
            }
        }
#pragma unroll
        for (int o = 16; o; o >>= 1) {
            s0 += __shfl_xor_sync(0xffffffffu, s0, o);
            q0 += __shfl_xor_sync(0xffffffffu, q0, o);
            s1 += __shfl_xor_sync(0xffffffffu, s1, o);
            q1 += __shfl_xor_sync(0xffffffffu, q1, o);
        }
        if (lane == 0) {
            int base = ((wm*4 + mf)*2)*4 + wn;
            sred[base]     = s0; ssred[base]     = q0;
            sred[base + 4] = s1; ssred[base + 4] = q1;
        }
    }
    __syncthreads();
#pragma unroll
    for (int mf = 0; mf < 4; mf++)
#pragma unroll
        for (int b = 0; b < 2; b++) {
            int base = ((wm*4 + mf)*2 + b)*4;
            float s = sred[base] + sred[base+1] + sred[base+2] + sred[base+3];
            float q = ssred[base] + ssred[base+1] + ssred[base+2] + ssred[base+3];
            float m_ = s * (1.f/784.f);
            mean_[mf][b] = m_;
            inv_[mf][b]  = rsqrtf(q * (1.f/784.f) - m_*m_ + 1e-5f);
        }
#pragma unroll
    for (int mf = 0; mf < 4; mf++) {
        int m0 = wm*64 + mf*16 + mrow;
        int ch0 = ocb + m0, ch1 = ch0 + 8;
        float g0 = gamma[ch0], g1 = gamma[ch1];
        float e0 = beta[ch0],  e1 = beta[ch1];
#pragma unroll
        for (int nf = 0; nf < 4; nf++) {
            int nb = wn*32 + nf*8 + ncol0;
#pragma unroll
            for (int r = 0; r < 4; r++) {
                int n = nb + (r & 1);
                if (n >= 98) continue;
                int b = (n >= 49); int p = n - b*49;
                float ga = (r < 2) ? g0 : g1;
                float be = (r < 2) ? e0 : e1;
                int ch   = (r < 2) ? ch0 : ch1;
                float v = (acc[mf][nf][r] - mean_[mf][b]) * inv_[mf][b] * ga + be;
                v = fmaxf(v, 0.f);
                long gi = ((long)(b0 + b)*C576 + ch)*49 + p;
                dstF[gi] = v;
                __nv_bfloat16 h = __float2bfloat16(v);
                outH[gi] = h;
                outL[gi] = __float2bfloat16(v - __bfloat162float(h));
            }
        }
    }
}

// =====================================================================
// conv0 (FFMA2): 3x3 s2 p1, 256->576, GN+ReLU; also emits bf16 hi/lo
// =====================================================================
#define C0_SMEM (34816 + 19008 + 224*4*2 + 64)
__global__ __launch_bounds__(224) void conv0_kernel(
    const float* __restrict__ x, const float* __restrict__ w,
    const float* __restrict__ bias, const float* __restrict__ gamma,
    const float* __restrict__ beta, float* __restrict__ dst,
    __nv_bfloat16* __restrict__ outH, __nv_bfloat16* __restrict__ outL)
{
    extern __shared__ char sm_raw[];
    float2* in_d  = (float2*)sm_raw;
    float*  w_s   = (float*)(sm_raw + 34816);
    float*  psum  = (float*)(sm_raw + 34816 + 19008);
    float*  psum2 = psum + 224;
    float*  gstat = psum2 + 224;

    const int b0  = blockIdx.y * 2;
    const int ocb = blockIdx.x * 64;
    const int tid = threadIdx.x;
    const int bh  = tid / 112;
    const int t   = tid % 112;
    const int row = t % 7;
    const int og  = t / 7;
    const int b   = b0 + bh;

    u64t accP[2][7];
#pragma unroll
    for (int op = 0; op < 2; op++) {
        u64t bv = pack2(bias[ocb + og*4 + op*2], bias[ocb + og*4 + op*2 + 1]);
#pragma unroll
        for (int xo = 0; xo < 7; xo++) accP[op][xo] = bv;
    }

    for (int ic0 = 0; ic0 < 256; ic0 += 8) {
        for (int li = tid; li < 8*64*9; li += 224) {
            int ocl = li / 72; int rem = li % 72; int icl = rem / 9; int tap = rem % 9;
            w_s[(icl*9 + tap)*66 + ocl] = w[((ocb + ocl)*256 + ic0 + icl)*9 + tap];
        }
        for (int li = tid; li < 2*8*256; li += 224) {
            int bb = li / 2048; int rem = li % 2048;
            int icl = rem >> 8; int r2 = rem & 255; int yy = r2 >> 4; int xx = r2 & 15;
            float v = 0.f;
            if (yy >= 1 && yy <= 14 && xx >= 1 && xx <= 14)
                v = x[((b0 + bb)*256 + ic0 + icl)*196 + (yy - 1)*14 + xx - 1];
            in_d[((bb*8 + icl)*16 + yy)*17 + xx] = make_float2(v, v);
        }
        __syncthreads();
#pragma unroll 1
        for (int ic = 0; ic < 8; ic++) {
#pragma unroll
            for (int dy = 0; dy < 3; dy++) {
                const u64t* vrow = (const u64t*)&in_d[((bh*8 + ic)*16 + 2*row + dy)*17];
                u64t vb[15];
#pragma unroll
                for (int k = 0; k < 15; k++) vb[k] = vrow[k];
#pragma unroll
                for (int op = 0; op < 2; op++) {
                    const float* wr = &w_s[(ic*9 + dy*3)*66 + og*4 + op*2];
                    u64t w0 = *(const u64t*)(wr);
                    u64t w1 = *(const u64t*)(wr + 66);
                    u64t w2 = *(const u64t*)(wr + 132);
#pragma unroll
                    for (int xo = 0; xo < 7; xo++)
                        accP[op][xo] = fma2(w0, vb[2*xo],
                                       fma2(w1, vb[2*xo+1],
                                       fma2(w2, vb[2*xo+2], accP[op][xo])));
                }
            }
        }
        __syncthreads();
    }

    float accf[4][7];
    float s = 0.f, s2 = 0.f;
#pragma unroll
    for (int op = 0; op < 2; op++)
#pragma unroll
        for (int xo = 0; xo < 7; xo++) {
            float a, q; unpack2(accP[op][xo], a, q);
            accf[op*2][xo] = a; accf[op*2+1][xo] = q;
            s += a + q; s2 += a*a + q*q;
        }
    psum[tid] = s; psum2[tid] = s2;
    __syncthreads();
    if ((tid % 28) == 0) {
        float a = 0.f, a2 = 0.f;
        for (int i = 0; i < 28; i++) { a += psum[tid + i]; a2 += psum2[tid + i]; }
        float m   = a  * (1.f/784.f);
        float var = a2 * (1.f/784.f) - m*m;
        gstat[tid/28]     = m;
        gstat[8 + tid/28] = rsqrtf(var + 1e-5f);
    }
    __syncthreads();
    {
        int c = tid / 28;
        float m = gstat[c], inv = gstat[8 + c];
#pragma unroll
        for (int oi = 0; oi < 4; oi++) {
            int ch = ocb + og*4 + oi;
            float ga = gamma[ch], be = beta[ch];
#pragma unroll
            for (int xo = 0; xo < 7; xo++) {
                float vv = fmaxf((accf[oi][xo] - m) * inv * ga + be, 0.f);
                long gi = ((long)b*C576 + ch)*49 + row*7 + xo;
                dst[gi] = vv;
                __nv_bfloat16 h = __float2bfloat16(vv);
                outH[gi] = h;
                outL[gi] = __float2bfloat16(vv - __bfloat162float(h));
            }
        }
    }
}

// ---------------- message passing ----------------
__global__ __launch_bounds__(256) void mp_kernel(
    const float* __restrict__ src, const float* __restrict__ dw_w,
    const float* __restrict__ dw_b, const float* __restrict__ pw_w,
    const float* __restrict__ pw_b, float* __restrict__ msgs)
{
    const int e = blockIdx.x, b = blockIdx.y;
    const int sg = c_esrc[e];
    __shared__ float in_pad[64][11][11];
    __shared__ float t_s[64][49];
    const int tid = threadIdx.x;

    for (int li = tid; li < 64*121; li += 256) {
        int c = li / 121; int rem = li % 121; int yy = rem / 11; int xx = rem % 11;
        float v = 0.f;
        if (yy >= 2 && yy <= 8 && xx >= 2 && xx <= 8)
            v = src[((b*C576 + sg*64 + c)*7 + yy - 2)*7 + xx - 2];
        in_pad[c][yy][xx] = v;
    }
    __syncthreads();
    for (int idx = tid; idx < 64*49; idx += 256) {
        int c = idx / 49, p = idx % 49, y = p / 7, xx = p % 7;
        float acc = dw_b[e*64 + c];
        const float* wp = dw_w + (e*64 + c)*25;
#pragma unroll
        for (int ky = 0; ky < 5; ky++)
#pragma unroll
            for (int kx = 0; kx < 5; kx++)
                acc = fmaf(in_pad[c][y + ky][xx + kx], wp[ky*5 + kx], acc);
        t_s[c][p] = acc;
    }
    __syncthreads();
    for (int idx = tid; idx < 64*49; idx += 256) {
        int o = idx / 49, p = idx % 49;
        float acc = pw_b[e*64 + o];
        const float* wp = pw_w + (e*64 + o)*64;
#pragma unroll 8
        for (int c = 0; c < 64; c++)
            acc = fmaf(wp[c], t_s[c][p], acc);
        msgs[((e*BATCH + b)*64 + o)*49 + p] = acc;
    }
}

__global__ __launch_bounds__(256) void gather_kernel(
    const float* __restrict__ base, const float* __restrict__ msgs,
    float* __restrict__ out)
{
    int i = blockIdx.x * blockDim.x + threadIdx.x;
    if (i >= BATCH*C576*HW49) return;
    int b = i / (C576*HW49); int rem = i % (C576*HW49);
    int ch = rem / 49; int p = rem % 49;
    int g = ch >> 6; int o = ch & 63;
    float v = base[i];
    int e1 = c_doff[g + 1];
    for (int e = c_doff[g]; e < e1; e++)
        v += msgs[((e*BATCH + b)*64 + o)*49 + p];
    out[i] = v;
}

// ---------------- deconv1 + GN + ReLU ----------------
__global__ __launch_bounds__(256) void deconv1_kernel(
    const float* __restrict__ src, const float* __restrict__ w,
    const float* __restrict__ bias, const float* __restrict__ gamma,
    const float* __restrict__ beta, float* __restrict__ dst)
{
    const int g = blockIdx.x, b = blockIdx.y;
    __shared__ float in_s[64*49];
    __shared__ float red[256], red2[256];
    __shared__ float s_stats[2];
    const int tid = threadIdx.x;

    for (int li = tid; li < 64*49; li += 256)
        in_s[li] = src[(b*C576 + g*64)*49 + li];
    __syncthreads();

    const bool active = tid < 224;
    const int ocg = tid / 14;
    const int row = tid % 14;
    float acc[4][14];
    if (active) {
#pragma unroll
        for (int oi = 0; oi < 4; oi++)
#pragma unroll
            for (int ox = 0; ox < 14; ox++) acc[oi][ox] = 0.f;
        const int kp = (row + 1) & 1;
#pragma unroll 1
        for (int ic = 0; ic < 64; ic++) {
            const float* wbase = w + (((g*64 + ic)*64) + ocg*4) * 16;
#pragma unroll
            for (int t = 0; t < 2; t++) {
                int ky = kp + 2*t;
                int iy = (row + 1 - ky) >> 1;
                if (iy < 0 || iy >= 7) continue;
                float v[7];
#pragma unroll
                for (int j = 0; j < 7; j++) v[j] = in_s[ic*49 + iy*7 + j];
#pragma unroll
                for (int kx = 0; kx < 4; kx++) {
                    float w4[4];
#pragma unroll
                    for (int oi = 0; oi < 4; oi++)
                        w4[oi] = __ldg(wbase + oi*16 + ky*4 + kx);
#pragma unroll
                    for (int j = 0; j < 7; j++) {
                        const int ox = 2*j - 1 + kx;
                        if (ox < 0 || ox > 13) continue;
#pragma unroll
                        for (int oi = 0; oi < 4; oi++)
                            acc[oi][ox] = fmaf(w4[oi], v[j], acc[oi][ox]);
                    }
                }
            }
        }
    }
    float lsum = 0.f, lsum2 = 0.f;
    if (active) {
#pragma unroll
        for (int oi = 0; oi < 4; oi++) {
            float bv = bias[g*64 + ocg*4 + oi];
#pragma unroll
            for (int ox = 0; ox < 14; ox++) {
                float val = acc[oi][ox] + bv;
                acc[oi][ox] = val;
                lsum += val; lsum2 += val*val;
            }
        }
    }
    red[tid] = lsum; red2[tid] = lsum2;
    __syncthreads();
    for (int s = 128; s > 0; s >>= 1) {
        if (tid < s) { red[tid] += red[tid + s]; red2[tid] += red2[tid + s]; }
        __syncthreads();
    }
    if (tid == 0) {
        float m   = red[0]  * (1.f/12544.f);
        float var = red2[0] * (1.f/12544.f) - m*m;
        s_stats[0] = m;
        s_stats[1] = rsqrtf(var + 1e-5f);
    }
    __syncthreads();
    if (active) {
        float m = s_stats[0], inv = s_stats[1];
#pragma unroll
        for (int oi = 0; oi < 4; oi++) {
            int ch = g*64 + ocg*4 + oi;
            float ga = gamma[ch], be = beta[ch];
#pragma unroll
            for (int ox = 0; ox < 14; ox++) {
                float val = (acc[oi][ox] - m) * inv * ga + be;
                dst[(b*C576 + ch)*196 + row*14 + ox] = fmaxf(val, 0.f);
            }
        }
    }
}

// ---------------- up2 ----------------
__global__ __launch_bounds__(64) void up2_kernel(
    const float* __restrict__ src, const float* __restrict__ w,
    const float* __restrict__ bias, float* __restrict__ out)
{
    const int g = blockIdx.x, b = blockIdx.y;
    const int tid = threadIdx.x;
    if (tid >= 49) return;
    const int r2 = tid / 7, c2 = tid % 7;
    const int iy0 = 2*r2 - 1, ix0 = 2*c2 - 1;
    const int TK[4][2] = {{1,3},{0,2},{1,3},{0,2}};
    const int TR[4][2] = {{1,0},{2,1},{2,1},{3,2}};
    float acc[4][4];
#pragma unroll
    for (int a = 0; a < 4; a++)
#pragma unroll
        for (int c = 0; c < 4; c++) acc[a][c] = 0.f;
#pragma unroll 1
    for (int ic = 0; ic < 64; ic++) {
        const float* ib = src + (b*C576 + g*64 + ic)*196;
        float vin[4][4];
#pragma unroll
        for (int a = 0; a < 4; a++) {
            int iy = iy0 + a;
#pragma unroll
            for (int c = 0; c < 4; c++) {
                int ix = ix0 + c;
                vin[a][c] = (iy >= 0 && iy < 14 && ix >= 0 && ix < 14)
                          ? __ldg(ib + iy*14 + ix) : 0.f;
            }
        }
        float w16[16];
#pragma unroll
        for (int t = 0; t < 16; t++) w16[t] = __ldg(w + (g*64 + ic)*16 + t);
#pragma unroll
        for (int dy = 0; dy < 4; dy++)
#pragma unroll
            for (int dx = 0; dx < 4; dx++)
#pragma unroll
                for (int i = 0; i < 2; i++)
#pragma unroll
                    for (int j = 0; j < 2; j++)
                        acc[dy][dx] = fmaf(w16[TK[dy][i]*4 + TK[dx][j]],
                                           vin[TR[dy][i]][TR[dx][j]], acc[dy][dx]);
    }
    const float bz = bias[g];
#pragma unroll
    for (int dy = 0; dy < 4; dy++)
#pragma unroll
        for (int dx = 0; dx < 4; dx++)
            out[(b*9 + g)*784 + (4*r2 + dy)*28 + (4*c2 + dx)] = acc[dy][dx] + bz;
}

// =====================================================================
// host launch
// =====================================================================
extern "C" void kernel_launch(void* const* d_in, const int* in_sizes, int n_in,
                              void* d_out, int out_size)
{
    const float* x        = (const float*)d_in[0];
    const float* convs_w0 = (const float*)d_in[1];
    const float* convs_b0 = (const float*)d_in[2];
    const float* convs_w  = (const float*)d_in[3];
    const float* convs_b  = (const float*)d_in[4];
    const float* gn_gamma = (const float*)d_in[5];
    const float* gn_beta  = (const float*)d_in[6];
    const float* fo_dw_w  = (const float*)d_in[7];
    const float* fo_dw_b  = (const float*)d_in[8];
    const float* fo_pw_w  = (const float*)d_in[9];
    const float* fo_pw_b  = (const float*)d_in[10];
    const float* so_dw_w  = (const float*)d_in[11];
    const float* so_dw_b  = (const float*)d_in[12];
    const float* so_pw_w  = (const float*)d_in[13];
    const float* so_pw_b  = (const float*)d_in[14];
    const float* up1_w    = (const float*)d_in[15];
    const float* up1_b    = (const float*)d_in[16];
    const float* sbn1_g   = (const float*)d_in[17];
    const float* sbn1_b   = (const float*)d_in[18];
    const float* up2_w    = (const float*)d_in[19];
    const float* up2_b    = (const float*)d_in[20];
    float* out = (float*)d_out;

    float *bufA, *bufB, *first, *second, *msgs, *headbuf;
    __nv_bfloat16 *whi, *wlo, *hA, *lA, *hB, *lB;
    cudaGetSymbolAddress((void**)&bufA,    g_bufA);
    cudaGetSymbolAddress((void**)&bufB,    g_bufB);
    cudaGetSymbolAddress((void**)&first,   g_first);
    cudaGetSymbolAddress((void**)&second,  g_second);
    cudaGetSymbolAddress((void**)&msgs,    g_msgs);
    cudaGetSymbolAddress((void**)&headbuf, g_head);
    cudaGetSymbolAddress((void**)&whi,     g_whi);
    cudaGetSymbolAddress((void**)&wlo,     g_wlo);
    cudaGetSymbolAddress((void**)&hA,      g_hA);
    cudaGetSymbolAddress((void**)&lA,      g_lA);
    cudaGetSymbolAddress((void**)&hB,      g_hB);
    cudaGetSymbolAddress((void**)&lB,      g_lB);

    cudaFuncSetAttribute(conv0_kernel, cudaFuncAttributeMaxDynamicSharedMemorySize, C0_SMEM);
    cudaFuncSetAttribute(conv_gemm_kernel, cudaFuncAttributeMaxDynamicSharedMemorySize, CG_SMEM);

    {
        long total = 7L*9*576*576;
        split_w_kernel<<<(unsigned)((total + 255)/256), 256>>>(convs_w, whi, wlo);
    }
    conv0_kernel<<<dim3(9, 32), 224, C0_SMEM>>>(x, convs_w0, convs_b0,
                                                gn_gamma, gn_beta, bufA, hA, lA);
    for (int l = 0; l < 7; l++) {
        const __nv_bfloat16* iH = (l % 2 == 0) ? hA : hB;
        const __nv_bfloat16* iL = (l % 2 == 0) ? lA : lB;
        __nv_bfloat16* oH = (l % 2 == 0) ? hB : hA;
        __nv_bfloat16* oL = (l % 2 == 0) ? lB : lA;
        float* d = (l % 2 == 0) ? bufB : bufA;
        conv_gemm_kernel<<<dim3(5, 32), 256, CG_SMEM>>>(iH, iL,
            whi + (long)l*9*576*576, wlo + (long)l*9*576*576,
            convs_b + l*576, gn_gamma + (l+1)*576, gn_beta + (l+1)*576,
            d, oH, oL);
    }
    // h in bufB (l=6 writes bufB)

    mp_kernel<<<dim3(NEDGE, BATCH), 256>>>(bufB, fo_dw_w, fo_dw_b, fo_pw_w, fo_pw_b, msgs);
    gather_kernel<<<(BATCH*C576*HW49 + 255)/256, 256>>>(bufB, msgs, first);
    mp_kernel<<<dim3(NEDGE, BATCH), 256>>>(first, so_dw_w, so_dw_b, so_pw_w, so_pw_b, msgs);
    gather_kernel<<<(BATCH*C576*HW49 + 255)/256, 256>>>(bufB, msgs, second);

    deconv1_kernel<<<dim3(9, BATCH), 256>>>(bufB, up1_w, up1_b, sbn1_g, sbn1_b, headbuf);
    up2_kernel<<<dim3(9, BATCH), 64>>>(headbuf, up2_w, up2_b, out);
    deconv1_kernel<<<dim3(9, BATCH), 256>>>(second, up1_w, up1_b, sbn1_g, sbn1_b, headbuf);
    up2_kernel<<<dim3(9, BATCH), 64>>>(headbuf, up2_w, up2_b, out + BATCH*9*784);

    (void)in_sizes; (void)n_in; (void)out_size;
}

// round 16
// speedup vs baseline: 1.0066x; 1.0066x over previous
#include <cuda_runtime.h>
#include <cuda_bf16.h>
#include <cstdint>

#define BATCH 64
#define C576  576
#define HW49  49
#define NEDGE 24

__device__ float g_bufA[BATCH*C576*HW49];
__device__ float g_bufB[BATCH*C576*HW49];
__device__ float g_first[BATCH*C576*HW49];
__device__ float g_second[BATCH*C576*HW49];
__device__ float g_msgs[NEDGE*BATCH*64*HW49];
__device__ float g_head[BATCH*C576*196];
__device__ __nv_bfloat16 g_whi[7L*9*576*576];
__device__ __nv_bfloat16 g_wlo[7L*9*576*576];
__device__ __nv_bfloat16 g_hA[BATCH*C576*HW49];
__device__ __nv_bfloat16 g_lA[BATCH*C576*HW49];
__device__ __nv_bfloat16 g_hB[BATCH*C576*HW49];
__device__ __nv_bfloat16 g_lB[BATCH*C576*HW49];

__constant__ int c_esrc[NEDGE] = {1,3, 0,2,4, 1,5, 0,4,6, 1,3,5,7, 2,4,8, 3,7, 4,6,8, 5,7};
__constant__ int c_doff[10]    = {0,2,5,7,10,14,17,19,22,24};
__constant__ int c_ocb[5]      = {0, 128, 256, 384, 448};

typedef unsigned long long u64t;
__device__ __forceinline__ u64t pack2(float x, float y) {
    u64t r; asm("mov.b64 %0, {%1, %2};" : "=l"(r) : "f"(x), "f"(y)); return r;
}
__device__ __forceinline__ u64t fma2(u64t a, u64t b, u64t c) {
    u64t d; asm("fma.rn.f32x2 %0, %1, %2, %3;" : "=l"(d) : "l"(a), "l"(b), "l"(c)); return d;
}
__device__ __forceinline__ void unpack2(u64t p, float& x, float& y) {
    asm("mov.b64 {%0, %1}, %2;" : "=f"(x), "=f"(y) : "l"(p));
}
__device__ __forceinline__ uint32_t smem_u32(const void* p) {
    uint32_t a;
    asm("{ .reg .u64 t; cvta.to.shared.u64 t, %1; cvt.u32.u64 %0, t; }" : "=r"(a) : "l"(p));
    return a;
}
__device__ __forceinline__ void ldsm_x4(uint32_t* r, uint32_t addr) {
    asm volatile("ldmatrix.sync.aligned.m8n8.x4.shared.b16 {%0,%1,%2,%3}, [%4];"
        : "=r"(r[0]), "=r"(r[1]), "=r"(r[2]), "=r"(r[3]) : "r"(addr));
}
__device__ __forceinline__ void ldsm_x2(uint32_t* r, uint32_t addr) {
    asm volatile("ldmatrix.sync.aligned.m8n8.x2.shared.b16 {%0,%1}, [%2];"
        : "=r"(r[0]), "=r"(r[1]) : "r"(addr));
}
__device__ __forceinline__ void mma_bf16(float* c, const uint32_t* a, const uint32_t* b) {
    asm volatile(
        "mma.sync.aligned.m16n8k16.row.col.f32.bf16.bf16.f32 "
        "{%0,%1,%2,%3}, {%4,%5,%6,%7}, {%8,%9}, {%0,%1,%2,%3};"
        : "+f"(c[0]), "+f"(c[1]), "+f"(c[2]), "+f"(c[3])
        : "r"(a[0]), "r"(a[1]), "r"(a[2]), "r"(a[3]), "r"(b[0]), "r"(b[1]));
}

// ---- weight split: fp32 -> bf16 hi/lo, layout [(l*9+t)*576+oc][ic] ----
__global__ void split_w_kernel(const float* __restrict__ w,
                               __nv_bfloat16* __restrict__ whi,
                               __nv_bfloat16* __restrict__ wlo)
{
    long i = (long)blockIdx.x * blockDim.x + threadIdx.x;
    if (i >= 7L*9*576*576) return;
    int ic = i % 576; long r = i / 576;
    int oc = r % 576; long r2 = r / 576;
    int t  = r2 % 9;  int l = (int)(r2 / 9);
    float v = w[(((long)(l*576 + oc))*576 + ic)*9 + t];
    __nv_bfloat16 hi = __float2bfloat16(v);
    whi[i] = hi;
    wlo[i] = __float2bfloat16(v - __bfloat162float(hi));
}

// =====================================================================
// conv1 via mma.sync bf16 hi/lo implicit GEMM, taps folded into K.
// grid (5 Mtiles, 32 bpairs), block 256 (8 warps: 2M x 4N).
// Per ic-chunk (16 ic): K = 144 = 9 taps x 16 ic (t-major).
// smem (dynamic, stride 152 elems = 304B, conflict-free for ldmatrix):
//   AsH 0, AsL 38912, BsH 77824, BsL 116736,
//   aH_s 155648 (5376), aL_s 161024 (5376), sred 166400, ssred 166656
// =====================================================================
#define STR 152
#define CG_SMEM 166912
__global__ __launch_bounds__(256, 1) void conv_gemm_kernel(
    const __nv_bfloat16* __restrict__ actH, const __nv_bfloat16* __restrict__ actL,
    const __nv_bfloat16* __restrict__ wHi,  const __nv_bfloat16* __restrict__ wLo,
    const float* __restrict__ bias, const float* __restrict__ gamma,
    const float* __restrict__ beta, float* __restrict__ dstF,
    __nv_bfloat16* __restrict__ outH, __nv_bfloat16* __restrict__ outL)
{
    extern __shared__ char sm[];
    __nv_bfloat16* AsH  = (__nv_bfloat16*)(sm);
    __nv_bfloat16* AsL  = (__nv_bfloat16*)(sm + 38912);
    __nv_bfloat16* BsH  = (__nv_bfloat16*)(sm + 77824);
    __nv_bfloat16* BsL  = (__nv_bfloat16*)(sm + 116736);
    __nv_bfloat16* aH_s = (__nv_bfloat16*)(sm + 155648);   // [2][16][84]
    __nv_bfloat16* aL_s = (__nv_bfloat16*)(sm + 161024);
    float* sred  = (float*)(sm + 166400);
    float* ssred = (float*)(sm + 166656);

    const int tid  = threadIdx.x;
    const int lane = tid & 31, w = tid >> 5;
    const int wm = w >> 2, wn = w & 3;
    const int ocb = c_ocb[blockIdx.x];
    const int b0  = blockIdx.y * 2;

    float acc[4][4][4];
#pragma unroll
    for (int i = 0; i < 4; i++)
#pragma unroll
        for (int j = 0; j < 4; j++)
#pragma unroll
            for (int r = 0; r < 4; r++) acc[i][j][r] = 0.f;

    // zero B rows 98..127 once (never rewritten)
    for (int i = tid; i < 30*STR; i += 256) {
        BsH[98*STR + i] = __nv_bfloat16(0.f);
        BsL[98*STR + i] = __nv_bfloat16(0.f);
    }

    const uint32_t asH = smem_u32(AsH), asL = smem_u32(AsL);
    const uint32_t bsH = smem_u32(BsH), bsL = smem_u32(BsL);
    const uint32_t aOff = (uint32_t)(lane & 15)*(STR*2) + (uint32_t)(lane >> 4)*16;
    const uint32_t bOff = (uint32_t)(lane & 7)*(STR*2) + (uint32_t)((lane >> 3) & 1)*16;

    for (int icc = 0; icc < 36; icc++) {
        const int ic0 = icc * 16;
        // stage padded activation frames (2 b x 16 ic x 9x9)
        for (int i = tid; i < 2592; i += 256) {
            int b = i / 1296; int r = i % 1296;
            int icl = r / 81; int q = r % 81;
            int y = q / 9, x = q % 9;
            __nv_bfloat16 vh = __nv_bfloat16(0.f), vl = __nv_bfloat16(0.f);
            if (y >= 1 && y <= 7 && x >= 1 && x <= 7) {
                long gi = ((long)(b0 + b)*C576 + ic0 + icl)*49 + (y-1)*7 + (x-1);
                vh = actH[gi]; vl = actL[gi];
            }
            aH_s[(b*16 + icl)*84 + q] = vh;
            aL_s[(b*16 + icl)*84 + q] = vl;
        }
        __syncthreads();
        // build B once: B[n][t*16+icl] = act[icl][pixel shifted by tap t]
        for (int i = tid; i < 98*144; i += 256) {
            int n = i / 144, k = i % 144;
            int t = k >> 4, icl = k & 15;
            int b = (n >= 49); int p = n - b*49;
            int q = (p/7 + t/3)*9 + (p%7 + t%3);
            BsH[n*STR + k] = aH_s[(b*16 + icl)*84 + q];
            BsL[n*STR + k] = aL_s[(b*16 + icl)*84 + q];
        }
        // stage A: 128 oc x 144 k (uint4 = 8 elems per load)
        for (int i = tid; i < 2304; i += 256) {
            int r = i / 18, c = i % 18;
            int t = c >> 1, half = c & 1;
            long gofs = ((long)(t*576 + ocb + r))*576 + ic0 + half*8;
            *(uint4*)&AsH[r*STR + t*16 + half*8] = *(const uint4*)&wHi[gofs];
            *(uint4*)&AsL[r*STR + t*16 + half*8] = *(const uint4*)&wLo[gofs];
        }
        __syncthreads();
#pragma unroll 1
        for (int j = 0; j < 9; j++) {
            uint32_t fAH[4][4], fAL[4][4], fBH[4][2], fBL[4][2];
            const uint32_t jb = (uint32_t)j*32;
#pragma unroll
            for (int mf = 0; mf < 4; mf++) {
                uint32_t off = (uint32_t)(wm*64 + mf*16)*(STR*2) + aOff + jb;
                ldsm_x4(fAH[mf], asH + off);
                ldsm_x4(fAL[mf], asL + off);
            }
#pragma unroll
            for (int nf = 0; nf < 4; nf++) {
                uint32_t off = (uint32_t)(wn*32 + nf*8)*(STR*2) + bOff + jb;
                ldsm_x2(fBH[nf], bsH + off);
                ldsm_x2(fBL[nf], bsL + off);
            }
#pragma unroll
            for (int mf = 0; mf < 4; mf++)
#pragma unroll
                for (int nf = 0; nf < 4; nf++) {
                    mma_bf16(acc[mf][nf], fAH[mf], fBH[nf]);
                    mma_bf16(acc[mf][nf], fAH[mf], fBL[nf]);
                    mma_bf16(acc[mf][nf], fAL[mf], fBH[nf]);
                }
        }
        __syncthreads();
    }

    // ---- epilogue: bias + GN(36) + ReLU + stores (f32 + bf16 hi/lo) ----
    const int mrow  = lane >> 2;
    const int ncol0 = 2*(lane & 3);
    float mean_[4][2], inv_[4][2];
#pragma unroll
    for (int mf = 0; mf < 4; mf++) {
        int m0 = wm*64 + mf*16 + mrow;
        float bv0 = bias[ocb + m0], bv1 = bias[ocb + m0 + 8];
        float s0 = 0.f, s1 = 0.f, q0 = 0.f, q1 = 0.f;
#pragma unroll
        for (int nf = 0; nf < 4; nf++) {
            int nb = wn*32 + nf*8 + ncol0;
#pragma unroll
            for (int r = 0; r < 4; r++) {
                int n = nb + (r & 1);
                float v = acc[mf][nf][r] + ((r < 2) ? bv0 : bv1);
                acc[mf][nf][r] = v;
                if (n < 49)      { s0 += v; q0 += v*v; }
                else if (n < 98) { s1 += v; q1 += v*v; }
            }
        }
#pragma unroll
        for (int o = 16; o; o >>= 1) {
            s0 += __shfl_xor_sync(0xffffffffu, s0, o);
            q0 += __shfl_xor_sync(0xffffffffu, q0, o);
            s1 += __shfl_xor_sync(0xffffffffu, s1, o);
            q1 += __shfl_xor_sync(0xffffffffu, q1, o);
        }
        if (lane == 0) {
            int base = ((wm*4 + mf)*2)*4 + wn;
            sred[base]     = s0; ssred[base]     = q0;
            sred[base + 4] = s1; ssred[base + 4] = q1;
        }
    }
    __syncthreads();
#pragma unroll
    for (int mf = 0; mf < 4; mf++)
#pragma unroll
        for (int b = 0; b < 2; b++) {
            int base = ((wm*4 + mf)*2 + b)*4;
            float s = sred[base] + sred[base+1] + sred[base+2] + sred[base+3];
            float q = ssred[base] + ssred[base+1] + ssred[base+2] + ssred[base+3];
            float m_ = s * (1.f/784.f);
            mean_[mf][b] = m_;
            inv_[mf][b]  = rsqrtf(q * (1.f/784.f) - m_*m_ + 1e-5f);
        }
#pragma unroll
    for (int mf = 0; mf < 4; mf++) {
        int m0 = wm*64 + mf*16 + mrow;
        int ch0 = ocb + m0, ch1 = ch0 + 8;
        float g0 = gamma[ch0], g1 = gamma[ch1];
        float e0 = beta[ch0],  e1 = beta[ch1];
#pragma unroll
        for (int nf = 0; nf < 4; nf++) {
            int nb = wn*32 + nf*8 + ncol0;
#pragma unroll
            for (int r = 0; r < 4; r++) {
                int n = nb + (r & 1);
                if (n >= 98) continue;
                int b = (n >= 49); int p = n - b*49;
                float ga = (r < 2) ? g0 : g1;
                float be = (r < 2) ? e0 : e1;
                int ch   = (r < 2) ? ch0 : ch1;
                float v = (acc[mf][nf][r] - mean_[mf][b]) * inv_[mf][b] * ga + be;
                v = fmaxf(v, 0.f);
                long gi = ((long)(b0 + b)*C576 + ch)*49 + p;
                dstF[gi] = v;
                __nv_bfloat16 h = __float2bfloat16(v);
                outH[gi] = h;
                outL[gi] = __float2bfloat16(v - __bfloat162float(h));
            }
        }
    }
}

// =====================================================================
// conv0 (FFMA2): 3x3 s2 p1, 256->576, GN+ReLU; also emits bf16 hi/lo
// =====================================================================
#define C0_SMEM (34816 + 19008 + 224*4*2 + 64)
__global__ __launch_bounds__(224) void conv0_kernel(
    const float* __restrict__ x, const float* __restrict__ w,
    const float* __restrict__ bias, const float* __restrict__ gamma,
    const float* __restrict__ beta, float* __restrict__ dst,
    __nv_bfloat16* __restrict__ outH, __nv_bfloat16* __restrict__ outL)
{
    extern __shared__ char sm_raw[];
    float2* in_d  = (float2*)sm_raw;
    float*  w_s   = (float*)(sm_raw + 34816);
    float*  psum  = (float*)(sm_raw + 34816 + 19008);
    float*  psum2 = psum + 224;
    float*  gstat = psum2 + 224;

    const int b0  = blockIdx.y * 2;
    const int ocb = blockIdx.x * 64;
    const int tid = threadIdx.x;
    const int bh  = tid / 112;
    const int t   = tid % 112;
    const int row = t % 7;
    const int og  = t / 7;
    const int b   = b0 + bh;

    u64t accP[2][7];
#pragma unroll
    for (int op = 0; op < 2; op++) {
        u64t bv = pack2(bias[ocb + og*4 + op*2], bias[ocb + og*4 + op*2 + 1]);
#pragma unroll
        for (int xo = 0; xo < 7; xo++) accP[op][xo] = bv;
    }

    for (int ic0 = 0; ic0 < 256; ic0 += 8) {
        for (int li = tid; li < 8*64*9; li += 224) {
            int ocl = li / 72; int rem = li % 72; int icl = rem / 9; int tap = rem % 9;
            w_s[(icl*9 + tap)*66 + ocl] = w[((ocb + ocl)*256 + ic0 + icl)*9 + tap];
        }
        for (int li = tid; li < 2*8*256; li += 224) {
            int bb = li / 2048; int rem = li % 2048;
            int icl = rem >> 8; int r2 = rem & 255; int yy = r2 >> 4; int xx = r2 & 15;
            float v = 0.f;
            if (yy >= 1 && yy <= 14 && xx >= 1 && xx <= 14)
                v = x[((b0 + bb)*256 + ic0 + icl)*196 + (yy - 1)*14 + xx - 1];
            in_d[((bb*8 + icl)*16 + yy)*17 + xx] = make_float2(v, v);
        }
        __syncthreads();
#pragma unroll 1
        for (int ic = 0; ic < 8; ic++) {
#pragma unroll
            for (int dy = 0; dy < 3; dy++) {
                const u64t* vrow = (const u64t*)&in_d[((bh*8 + ic)*16 + 2*row + dy)*17];
                u64t vb[15];
#pragma unroll
                for (int k = 0; k < 15; k++) vb[k] = vrow[k];
#pragma unroll
                for (int op = 0; op < 2; op++) {
                    const float* wr = &w_s[(ic*9 + dy*3)*66 + og*4 + op*2];
                    u64t w0 = *(const u64t*)(wr);
                    u64t w1 = *(const u64t*)(wr + 66);
                    u64t w2 = *(const u64t*)(wr + 132);
#pragma unroll
                    for (int xo = 0; xo < 7; xo++)
                        accP[op][xo] = fma2(w0, vb[2*xo],
                                       fma2(w1, vb[2*xo+1],
                                       fma2(w2, vb[2*xo+2], accP[op][xo])));
                }
            }
        }
        __syncthreads();
    }

    float accf[4][7];
    float s = 0.f, s2 = 0.f;
#pragma unroll
    for (int op = 0; op < 2; op++)
#pragma unroll
        for (int xo = 0; xo < 7; xo++) {
            float a, q; unpack2(accP[op][xo], a, q);
            accf[op*2][xo] = a; accf[op*2+1][xo] = q;
            s += a + q; s2 += a*a + q*q;
        }
    psum[tid] = s; psum2[tid] = s2;
    __syncthreads();
    if ((tid % 28) == 0) {
        float a = 0.f, a2 = 0.f;
        for (int i = 0; i < 28; i++) { a += psum[tid + i]; a2 += psum2[tid + i]; }
        float m   = a  * (1.f/784.f);
        float var = a2 * (1.f/784.f) - m*m;
        gstat[tid/28]     = m;
        gstat[8 + tid/28] = rsqrtf(var + 1e-5f);
    }
    __syncthreads();
    {
        int c = tid / 28;
        float m = gstat[c], inv = gstat[8 + c];
#pragma unroll
        for (int oi = 0; oi < 4; oi++) {
            int ch = ocb + og*4 + oi;
            float ga = gamma[ch], be = beta[ch];
#pragma unroll
            for (int xo = 0; xo < 7; xo++) {
                float vv = fmaxf((accf[oi][xo] - m) * inv * ga + be, 0.f);
                long gi = ((long)b*C576 + ch)*49 + row*7 + xo;
                dst[gi] = vv;
                __nv_bfloat16 h = __float2bfloat16(vv);
                outH[gi] = h;
                outL[gi] = __float2bfloat16(vv - __bfloat162float(h));
            }
        }
    }
}

// ---------------- message passing ----------------
__global__ __launch_bounds__(256) void mp_kernel(
    const float* __restrict__ src, const float* __restrict__ dw_w,
    const float* __restrict__ dw_b, const float* __restrict__ pw_w,
    const float* __restrict__ pw_b, float* __restrict__ msgs)
{
    const int e = blockIdx.x, b = blockIdx.y;
    const int sg = c_esrc[e];
    __shared__ float in_pad[64][11][11];
    __shared__ float t_s[64][49];
    const int tid = threadIdx.x;

    for (int li = tid; li < 64*121; li += 256) {
        int c = li / 121; int rem = li % 121; int yy = rem / 11; int xx = rem % 11;
        float v = 0.f;
        if (yy >= 2 && yy <= 8 && xx >= 2 && xx <= 8)
            v = src[((b*C576 + sg*64 + c)*7 + yy - 2)*7 + xx - 2];
        in_pad[c][yy][xx] = v;
    }
    __syncthreads();
    for (int idx = tid; idx < 64*49; idx += 256) {
        int c = idx / 49, p = idx % 49, y = p / 7, xx = p % 7;
        float acc = dw_b[e*64 + c];
        const float* wp = dw_w + (e*64 + c)*25;
#pragma unroll
        for (int ky = 0; ky < 5; ky++)
#pragma unroll
            for (int kx = 0; kx < 5; kx++)
                acc = fmaf(in_pad[c][y + ky][xx + kx], wp[ky*5 + kx], acc);
        t_s[c][p] = acc;
    }
    __syncthreads();
    for (int idx = tid; idx < 64*49; idx += 256) {
        int o = idx / 49, p = idx % 49;
        float acc = pw_b[e*64 + o];
        const float* wp = pw_w + (e*64 + o)*64;
#pragma unroll 8
        for (int c = 0; c < 64; c++)
            acc = fmaf(wp[c], t_s[c][p], acc);
        msgs[((e*BATCH + b)*64 + o)*49 + p] = acc;
    }
}

__global__ __launch_bounds__(256) void gather_kernel(
    const float* __restrict__ base, const float* __restrict__ msgs,
    float* __restrict__ out)
{
    int i = blockIdx.x * blockDim.x + threadIdx.x;
    if (i >= BATCH*C576*HW49) return;
    int b = i / (C576*HW49); int rem = i % (C576*HW49);
    int ch = rem / 49; int p = rem % 49;
    int g = ch >> 6; int o = ch & 63;
    float v = base[i];
    int e1 = c_doff[g + 1];
    for (int e = c_doff[g]; e < e1; e++)
        v += msgs[((e*BATCH + b)*64 + o)*49 + p];
    out[i] = v;
}

// ---------------- deconv1 + GN + ReLU ----------------
__global__ __launch_bounds__(256) void deconv1_kernel(
    const float* __restrict__ src, const float* __restrict__ w,
    const float* __restrict__ bias, const float* __restrict__ gamma,
    const float* __restrict__ beta, float* __restrict__ dst)
{
    const int g = blockIdx.x, b = blockIdx.y;
    __shared__ float in_s[64*49];
    __shared__ float red[256], red2[256];
    __shared__ float s_stats[2];
    const int tid = threadIdx.x;

    for (int li = tid; li < 64*49; li += 256)
        in_s[li] = src[(b*C576 + g*64)*49 + li];
    __syncthreads();

    const bool active = tid < 224;
    const int ocg = tid / 14;
    const int row = tid % 14;
    float acc[4][14];
    if (active) {
#pragma unroll
        for (int oi = 0; oi < 4; oi++)
#pragma unroll
            for (int ox = 0; ox < 14; ox++) acc[oi][ox] = 0.f;
        const int kp = (row + 1) & 1;
#pragma unroll 1
        for (int ic = 0; ic < 64; ic++) {
            const float* wbase = w + (((g*64 + ic)*64) + ocg*4) * 16;
#pragma unroll
            for (int t = 0; t < 2; t++) {
                int ky = kp + 2*t;
                int iy = (row + 1 - ky) >> 1;
                if (iy < 0 || iy >= 7) continue;
                float v[7];
#pragma unroll
                for (int j = 0; j < 7; j++) v[j] = in_s[ic*49 + iy*7 + j];
#pragma unroll
                for (int kx = 0; kx < 4; kx++) {
                    float w4[4];
#pragma unroll
                    for (int oi = 0; oi < 4; oi++)
                        w4[oi] = __ldg(wbase + oi*16 + ky*4 + kx);
#pragma unroll
                    for (int j = 0; j < 7; j++) {
                        const int ox = 2*j - 1 + kx;
                        if (ox < 0 || ox > 13) continue;
#pragma unroll
                        for (int oi = 0; oi < 4; oi++)
                            acc[oi][ox] = fmaf(w4[oi], v[j], acc[oi][ox]);
                    }
                }
            }
        }
    }
    float lsum = 0.f, lsum2 = 0.f;
    if (active) {
#pragma unroll
        for (int oi = 0; oi < 4; oi++) {
            float bv = bias[g*64 + ocg*4 + oi];
#pragma unroll
            for (int ox = 0; ox < 14; ox++) {
                float val = acc[oi][ox] + bv;
                acc[oi][ox] = val;
                lsum += val; lsum2 += val*val;
            }
        }
    }
    red[tid] = lsum; red2[tid] = lsum2;
    __syncthreads();
    for (int s = 128; s > 0; s >>= 1) {
        if (tid < s) { red[tid] += red[tid + s]; red2[tid] += red2[tid + s]; }
        __syncthreads();
    }
    if (tid == 0) {
        float m   = red[0]  * (1.f/12544.f);
        float var = red2[0] * (1.f/12544.f) - m*m;
        s_stats[0] = m;
        s_stats[1] = rsqrtf(var + 1e-5f);
    }
    __syncthreads();
    if (active) {
        float m = s_stats[0], inv = s_stats[1];
#pragma unroll
        for (int oi = 0; oi < 4; oi++) {
            int ch = g*64 + ocg*4 + oi;
            float ga = gamma[ch], be = beta[ch];
#pragma unroll
            for (int ox = 0; ox < 14; ox++) {
                float val = (acc[oi][ox] - m) * inv * ga + be;
                dst[(b*C576 + ch)*196 + row*14 + ox] = fmaxf(val, 0.f);
            }
        }
    }
}

// ---------------- up2 ----------------
__global__ __launch_bounds__(64) void up2_kernel(
    const float* __restrict__ src, const float* __restrict__ w,
    const float* __restrict__ bias, float* __restrict__ out)
{
    const int g = blockIdx.x, b = blockIdx.y;
    const int tid = threadIdx.x;
    if (tid >= 49) return;
    const int r2 = tid / 7, c2 = tid % 7;
    const int iy0 = 2*r2 - 1, ix0 = 2*c2 - 1;
    const int TK[4][2] = {{1,3},{0,2},{1,3},{0,2}};
    const int TR[4][2] = {{1,0},{2,1},{2,1},{3,2}};
    float acc[4][4];
#pragma unroll
    for (int a = 0; a < 4; a++)
#pragma unroll
        for (int c = 0; c < 4; c++) acc[a][c] = 0.f;
#pragma unroll 1
    for (int ic = 0; ic < 64; ic++) {
        const float* ib = src + (b*C576 + g*64 + ic)*196;
        float vin[4][4];
#pragma unroll
        for (int a = 0; a < 4; a++) {
            int iy = iy0 + a;
#pragma unroll
            for (int c = 0; c < 4; c++) {
                int ix = ix0 + c;
                vin[a][c] = (iy >= 0 && iy < 14 && ix >= 0 && ix < 14)
                          ? __ldg(ib + iy*14 + ix) : 0.f;
            }
        }
        float w16[16];
#pragma unroll
        for (int t = 0; t < 16; t++) w16[t] = __ldg(w + (g*64 + ic)*16 + t);
#pragma unroll
        for (int dy = 0; dy < 4; dy++)
#pragma unroll
            for (int dx = 0; dx < 4; dx++)
#pragma unroll
                for (int i = 0; i < 2; i++)
#pragma unroll
                    for (int j = 0; j < 2; j++)
                        acc[dy][dx] = fmaf(w16[TK[dy][i]*4 + TK[dx][j]],
                                           vin[TR[dy][i]][TR[dx][j]], acc[dy][dx]);
    }
    const float bz = bias[g];
#pragma unroll
    for (int dy = 0; dy < 4; dy++)
#pragma unroll
        for (int dx = 0; dx < 4; dx++)
            out[(b*9 + g)*784 + (4*r2 + dy)*28 + (4*c2 + dx)] = acc[dy][dx] + bz;
}

// =====================================================================
// host launch
// =====================================================================
extern "C" void kernel_launch(void* const* d_in, const int* in_sizes, int n_in,
                              void* d_out, int out_size)
{
    const float* x        = (const float*)d_in[0];
    const float* convs_w0 = (const float*)d_in[1];
    const float* convs_b0 = (const float*)d_in[2];
    const float* convs_w  = (const float*)d_in[3];
    const float* convs_b  = (const float*)d_in[4];
    const float* gn_gamma = (const float*)d_in[5];
    const float* gn_beta  = (const float*)d_in[6];
    const float* fo_dw_w  = (const float*)d_in[7];
    const float* fo_dw_b  = (const float*)d_in[8];
    const float* fo_pw_w  = (const float*)d_in[9];
    const float* fo_pw_b  = (const float*)d_in[10];
    const float* so_dw_w  = (const float*)d_in[11];
    const float* so_dw_b  = (const float*)d_in[12];
    const float* so_pw_w  = (const float*)d_in[13];
    const float* so_pw_b  = (const float*)d_in[14];
    const float* up1_w    = (const float*)d_in[15];
    const float* up1_b    = (const float*)d_in[16];
    const float* sbn1_g   = (const float*)d_in[17];
    const float* sbn1_b   = (const float*)d_in[18];
    const float* up2_w    = (const float*)d_in[19];
    const float* up2_b    = (const float*)d_in[20];
    float* out = (float*)d_out;

    float *bufA, *bufB, *first, *second, *msgs, *headbuf;
    __nv_bfloat16 *whi, *wlo, *hA, *lA, *hB, *lB;
    cudaGetSymbolAddress((void**)&bufA,    g_bufA);
    cudaGetSymbolAddress((void**)&bufB,    g_bufB);
    cudaGetSymbolAddress((void**)&first,   g_first);
    cudaGetSymbolAddress((void**)&second,  g_second);
    cudaGetSymbolAddress((void**)&msgs,    g_msgs);
    cudaGetSymbolAddress((void**)&headbuf, g_head);
    cudaGetSymbolAddress((void**)&whi,     g_whi);
    cudaGetSymbolAddress((void**)&wlo,     g_wlo);
    cudaGetSymbolAddress((void**)&hA,      g_hA);
    cudaGetSymbolAddress((void**)&lA,      g_lA);
    cudaGetSymbolAddress((void**)&hB,      g_hB);
    cudaGetSymbolAddress((void**)&lB,      g_lB);

    cudaFuncSetAttribute(conv0_kernel, cudaFuncAttributeMaxDynamicSharedMemorySize, C0_SMEM);
    cudaFuncSetAttribute(conv_gemm_kernel, cudaFuncAttributeMaxDynamicSharedMemorySize, CG_SMEM);

    {
        long total = 7L*9*576*576;
        split_w_kernel<<<(unsigned)((total + 255)/256), 256>>>(convs_w, whi, wlo);
    }
    conv0_kernel<<<dim3(9, 32), 224, C0_SMEM>>>(x, convs_w0, convs_b0,
                                                gn_gamma, gn_beta, bufA, hA, lA);
    for (int l = 0; l < 7; l++) {
        const __nv_bfloat16* iH = (l % 2 == 0) ? hA : hB;
        const __nv_bfloat16* iL = (l % 2 == 0) ? lA : lB;
        __nv_bfloat16* oH = (l % 2 == 0) ? hB : hA;
        __nv_bfloat16* oL = (l % 2 == 0) ? lB : lA;
        float* d = (l % 2 == 0) ? bufB : bufA;
        conv_gemm_kernel<<<dim3(5, 32), 256, CG_SMEM>>>(iH, iL,
            whi + (long)l*9*576*576, wlo + (long)l*9*576*576,
            convs_b + l*576, gn_gamma + (l+1)*576, gn_beta + (l+1)*576,
            d, oH, oL);
    }
    // h in bufB (l=6 writes bufB)

    mp_kernel<<<dim3(NEDGE, BATCH), 256>>>(bufB, fo_dw_w, fo_dw_b, fo_pw_w, fo_pw_b, msgs);
    gather_kernel<<<(BATCH*C576*HW49 + 255)/256, 256>>>(bufB, msgs, first);
    mp_kernel<<<dim3(NEDGE, BATCH), 256>>>(first, so_dw_w, so_dw_b, so_pw_w, so_pw_b, msgs);
    gather_kernel<<<(BATCH*C576*HW49 + 255)/256, 256>>>(bufB, msgs, second);

    deconv1_kernel<<<dim3(9, BATCH), 256>>>(bufB, up1_w, up1_b, sbn1_g, sbn1_b, headbuf);
    up2_kernel<<<dim3(9, BATCH), 64>>>(headbuf, up2_w, up2_b, out);
    deconv1_kernel<<<dim3(9, BATCH), 256>>>(second, up1_w, up1_b, sbn1_g, sbn1_b, headbuf);
    up2_kernel<<<dim3(9, BATCH), 64>>>(headbuf, up2_w, up2_b, out + BATCH*9*784);

    (void)in_sizes; (void)n_in; (void)out_size;
}